// round 9
// baseline (speedup 1.0000x reference)
#include <cuda_runtime.h>
#include <math.h>

#define U 8388608UL
__device__ __align__(256) float g_pool[11*U + 131072];

// ---------------- helpers ----------------
__device__ __forceinline__ float tf32r(float v) {
    unsigned u;
    asm("cvt.rna.tf32.f32 %0, %1;" : "=r"(u) : "f"(v));
    return __uint_as_float(u);
}
__device__ __forceinline__ void mma_tf32(float* c, const unsigned* a, const unsigned* b) {
    asm volatile(
        "mma.sync.aligned.m16n8k8.row.col.f32.tf32.tf32.f32 "
        "{%0,%1,%2,%3},{%4,%5,%6,%7},{%8,%9},{%0,%1,%2,%3};"
        : "+f"(c[0]), "+f"(c[1]), "+f"(c[2]), "+f"(c[3])
        : "r"(a[0]), "r"(a[1]), "r"(a[2]), "r"(a[3]), "r"(b[0]), "r"(b[1]));
}

// K=128 MMA pass over row-major smem tiles aT[m][k], wT[n][k] (ld 132)
// mode 0: raw(tf32), mode 1: per-row LN transform with gam/bet
__device__ __forceinline__ void mma_pass_k128(
    const float* __restrict__ aT, const float* __restrict__ wT,
    int wm, int wn, int g, int tig, int mode,
    const float* mr, const float* rr,
    const float* __restrict__ gam, const float* __restrict__ bet,
    float (&acc)[2][8][4])
{
    #pragma unroll
    for (int i = 0; i < 2; i++)
        #pragma unroll
        for (int j = 0; j < 8; j++)
            #pragma unroll
            for (int q = 0; q < 4; q++) acc[i][j][q] = 0.f;
    for (int ks = 0; ks < 128; ks += 8) {
        unsigned af[2][4], bf[8][2];
        float g0 = 0.f, g4 = 0.f, b0 = 0.f, b4 = 0.f;
        if (mode) { g0 = gam[ks+tig]; g4 = gam[ks+tig+4]; b0 = bet[ks+tig]; b4 = bet[ks+tig+4]; }
        #pragma unroll
        for (int mi = 0; mi < 2; mi++) {
            int r0i = (wm + mi*16 + g) * 132;
            int r1i = r0i + 8*132;
            float r0 = aT[r0i + ks + tig];
            float r1 = aT[r1i + ks + tig];
            float r2 = aT[r0i + ks + tig + 4];
            float r3 = aT[r1i + ks + tig + 4];
            if (mode) {
                r0 = fmaf((r0 - mr[mi*2+0])*rr[mi*2+0], g0, b0);
                r1 = fmaf((r1 - mr[mi*2+1])*rr[mi*2+1], g0, b0);
                r2 = fmaf((r2 - mr[mi*2+0])*rr[mi*2+0], g4, b4);
                r3 = fmaf((r3 - mr[mi*2+1])*rr[mi*2+1], g4, b4);
            }
            af[mi][0] = __float_as_uint(tf32r(r0));
            af[mi][1] = __float_as_uint(tf32r(r1));
            af[mi][2] = __float_as_uint(tf32r(r2));
            af[mi][3] = __float_as_uint(tf32r(r3));
        }
        #pragma unroll
        for (int ni = 0; ni < 8; ni++) {
            int nr = (wn + ni*8 + g) * 132;
            bf[ni][0] = __float_as_uint(wT[nr + ks + tig]);
            bf[ni][1] = __float_as_uint(wT[nr + ks + tig + 4]);
        }
        #pragma unroll
        for (int mi = 0; mi < 2; mi++)
            #pragma unroll
            for (int ni = 0; ni < 8; ni++)
                mma_tf32(acc[mi][ni], af[mi], bf[ni]);
    }
}

// ---------------- DWT ----------------
__global__ void dwt_kernel(const float* __restrict__ x, float* __restrict__ hllh,
                           float* __restrict__ yL, float* __restrict__ yHH)
{
    int i  = blockIdx.x;
    int cb = blockIdx.y;
    int b  = blockIdx.z;
    __shared__ float s[16][2][129];
    int tid = threadIdx.x;
    #pragma unroll
    for (int k = 0; k < 16; k++) {
        int e = tid + k*256;
        int cc = e >> 8, r = (e >> 7) & 1, col = e & 127;
        s[cc][r][col] = x[(((size_t)(b*128 + cb*16 + cc))*128 + 2*i + r)*128 + col];
    }
    __syncthreads();
    #pragma unroll
    for (int k = 0; k < 4; k++) {
        int e = tid + k*256;
        int cc = e & 15, j = e >> 4;
        float a  = s[cc][0][2*j], bb = s[cc][0][2*j+1];
        float c_ = s[cc][1][2*j], d  = s[cc][1][2*j+1];
        size_t token = (size_t)b*4096 + (size_t)i*64 + j;
        int c = cb*16 + cc;
        yL [token*128 + c]        = (a+bb+c_+d)*0.5f;
        yHH[token*128 + c]        = (a-bb-c_+d)*0.5f;
        hllh[token*256 + c]       = (a-bb+c_-d)*0.5f;
        hllh[token*256 + 128 + c] = (a+bb-c_-d)*0.5f;
    }
}

// ---------------- tf32 NT GEMM with register prefetch ----------------
__global__ __launch_bounds__(256, 2) void gemm_tf32(
    const float* __restrict__ A, size_t sAz, int lda,
    const float* __restrict__ B, size_t sBz, int ldb,
    float* __restrict__ C, size_t sCz, int ldc,
    int K, float scale, const float* __restrict__ bias,
    int epi, const float* __restrict__ aux)
{
    const float* Ab = A + (size_t)blockIdx.z * sAz;
    const float* Bb = B + (size_t)blockIdx.z * sBz;
    float* Cb = C + (size_t)blockIdx.z * sCz;
    int m0 = blockIdx.x * 128, n0 = blockIdx.y * 128;
    __shared__ float As[16][136], Bs[16][136];
    int tid = threadIdx.x;
    int wid = tid >> 5, lane = tid & 31;
    int g = lane >> 2, tig = lane & 3;
    int wm = (wid >> 1) * 32, wn = (wid & 1) * 64;
    float acc[2][8][4];
    #pragma unroll
    for (int i = 0; i < 2; i++)
        #pragma unroll
        for (int j = 0; j < 8; j++)
            #pragma unroll
            for (int q = 0; q < 4; q++) acc[i][j][q] = 0.f;

    int rowA = tid >> 2, kq = (tid & 3) * 4;
    float4 pa[2], pb[2];
    #pragma unroll
    for (int e = 0; e < 2; e++) {
        int r = rowA + e*64;
        pa[e] = *(const float4*)&Ab[(size_t)(m0 + r)*lda + kq];
        pb[e] = *(const float4*)&Bb[(size_t)(n0 + r)*ldb + kq];
    }
    for (int k0 = 0; k0 < K; k0 += 16) {
        #pragma unroll
        for (int e = 0; e < 2; e++) {
            int r = rowA + e*64;
            As[kq+0][r]=tf32r(pa[e].x); As[kq+1][r]=tf32r(pa[e].y);
            As[kq+2][r]=tf32r(pa[e].z); As[kq+3][r]=tf32r(pa[e].w);
            Bs[kq+0][r]=tf32r(pb[e].x); Bs[kq+1][r]=tf32r(pb[e].y);
            Bs[kq+2][r]=tf32r(pb[e].z); Bs[kq+3][r]=tf32r(pb[e].w);
        }
        __syncthreads();
        if (k0 + 16 < K) {
            #pragma unroll
            for (int e = 0; e < 2; e++) {
                int r = rowA + e*64;
                pa[e] = *(const float4*)&Ab[(size_t)(m0 + r)*lda + k0 + 16 + kq];
                pb[e] = *(const float4*)&Bb[(size_t)(n0 + r)*ldb + k0 + 16 + kq];
            }
        }
        #pragma unroll
        for (int ks = 0; ks < 16; ks += 8) {
            unsigned af[2][4], bf[8][2];
            #pragma unroll
            for (int mi = 0; mi < 2; mi++) {
                af[mi][0] = __float_as_uint(As[ks+tig  ][wm+mi*16+g  ]);
                af[mi][1] = __float_as_uint(As[ks+tig  ][wm+mi*16+g+8]);
                af[mi][2] = __float_as_uint(As[ks+tig+4][wm+mi*16+g  ]);
                af[mi][3] = __float_as_uint(As[ks+tig+4][wm+mi*16+g+8]);
            }
            #pragma unroll
            for (int ni = 0; ni < 8; ni++) {
                bf[ni][0] = __float_as_uint(Bs[ks+tig  ][wn+ni*8+g]);
                bf[ni][1] = __float_as_uint(Bs[ks+tig+4][wn+ni*8+g]);
            }
            #pragma unroll
            for (int mi = 0; mi < 2; mi++)
                #pragma unroll
                for (int ni = 0; ni < 8; ni++)
                    mma_tf32(acc[mi][ni], af[mi], bf[ni]);
        }
        __syncthreads();
    }
    #pragma unroll
    for (int mi = 0; mi < 2; mi++)
        #pragma unroll
        for (int half = 0; half < 2; half++) {
            int m = m0 + wm + mi*16 + g + half*8;
            #pragma unroll
            for (int ni = 0; ni < 8; ni++) {
                int n = n0 + wn + ni*8 + 2*tig;
                float v0 = acc[mi][ni][half*2+0]*scale;
                float v1 = acc[mi][ni][half*2+1]*scale;
                if (bias) { v0 += bias[n]; v1 += bias[n+1]; }
                if (epi == 1) { v0 = v0*normcdff(v0); v1 = v1*normcdff(v1); }
                if (aux) { v0 -= aux[(size_t)m*ldc+n]; v1 -= aux[(size_t)m*ldc+n+1]; }
                *(float2*)&Cb[(size_t)m*ldc + n] = make_float2(v0, v1);
            }
        }
}

// ---------------- fused implicit-GEMM l1 conv (4x4, s2, p1, relu) ----------------
__global__ __launch_bounds__(256, 2) void conv_l1_tf32(
    const float* __restrict__ x, const float* __restrict__ w,
    const float* __restrict__ bias, float* __restrict__ dw)
{
    int blk = blockIdx.x;
    int b   = blockIdx.z;
    int oh0 = blk*2;
    __shared__ float patch[8][6][132];
    __shared__ float As[16][136], Bs[16][136];
    int tid = threadIdx.x;
    int wid = tid >> 5, lane = tid & 31;
    int g = lane >> 2, tig = lane & 3;
    int wm = (wid >> 1) * 32, wn = (wid & 1) * 64;
    float acc[2][8][4];
    #pragma unroll
    for (int i = 0; i < 2; i++)
        #pragma unroll
        for (int j = 0; j < 8; j++)
            #pragma unroll
            for (int q = 0; q < 4; q++) acc[i][j][q] = 0.f;

    int t = tid & 127, kkq = (tid >> 7) * 8;
    int ohl = t >> 6, ow = t & 63;
    int coB = tid >> 1, kbB = (tid & 1) * 8;

    for (int ci0 = 0; ci0 < 128; ci0 += 8) {
        for (int e = tid; e < 8*6*130; e += 256) {
            int cil = e / 780;
            int rem = e - cil*780;
            int r = rem / 130, cc = rem - r*130;
            int gr = 2*oh0 - 1 + r, gc = cc - 1;
            float v = 0.f;
            if ((unsigned)gr < 128u && (unsigned)gc < 128u)
                v = x[(((size_t)b*128 + ci0 + cil)*128 + gr)*128 + gc];
            patch[cil][r][cc] = tf32r(v);
        }
        __syncthreads();
        #pragma unroll 1
        for (int cil = 0; cil < 8; cil++) {
            int kbase = (ci0 + cil) * 16;
            #pragma unroll
            for (int i = 0; i < 8; i++) {
                int kk = kkq + i;
                int kh = kk >> 2, kw = kk & 3;
                As[kk][t] = patch[cil][2*ohl + kh][2*ow + kw];
            }
            {
                float4 w0 = *(const float4*)&w[(size_t)coB*2048 + kbase + kbB];
                float4 w1 = *(const float4*)&w[(size_t)coB*2048 + kbase + kbB + 4];
                Bs[kbB+0][coB]=tf32r(w0.x); Bs[kbB+1][coB]=tf32r(w0.y);
                Bs[kbB+2][coB]=tf32r(w0.z); Bs[kbB+3][coB]=tf32r(w0.w);
                Bs[kbB+4][coB]=tf32r(w1.x); Bs[kbB+5][coB]=tf32r(w1.y);
                Bs[kbB+6][coB]=tf32r(w1.z); Bs[kbB+7][coB]=tf32r(w1.w);
            }
            __syncthreads();
            #pragma unroll
            for (int ks = 0; ks < 16; ks += 8) {
                unsigned af[2][4], bf[8][2];
                #pragma unroll
                for (int mi = 0; mi < 2; mi++) {
                    af[mi][0] = __float_as_uint(As[ks+tig  ][wm+mi*16+g  ]);
                    af[mi][1] = __float_as_uint(As[ks+tig  ][wm+mi*16+g+8]);
                    af[mi][2] = __float_as_uint(As[ks+tig+4][wm+mi*16+g  ]);
                    af[mi][3] = __float_as_uint(As[ks+tig+4][wm+mi*16+g+8]);
                }
                #pragma unroll
                for (int ni = 0; ni < 8; ni++) {
                    bf[ni][0] = __float_as_uint(Bs[ks+tig  ][wn+ni*8+g]);
                    bf[ni][1] = __float_as_uint(Bs[ks+tig+4][wn+ni*8+g]);
                }
                #pragma unroll
                for (int mi = 0; mi < 2; mi++)
                    #pragma unroll
                    for (int ni = 0; ni < 8; ni++)
                        mma_tf32(acc[mi][ni], af[mi], bf[ni]);
            }
            __syncthreads();
        }
    }
    #pragma unroll
    for (int mi = 0; mi < 2; mi++)
        #pragma unroll
        for (int half = 0; half < 2; half++) {
            int midx = wm + mi*16 + g + half*8;
            size_t token = (size_t)b*4096 + (size_t)blk*128 + midx;
            #pragma unroll
            for (int ni = 0; ni < 8; ni++) {
                int n = wn + ni*8 + 2*tig;
                float v0 = fmaxf(acc[mi][ni][half*2+0] + bias[n],   0.f);
                float v1 = fmaxf(acc[mi][ni][half*2+1] + bias[n+1], 0.f);
                *(float2*)&dw[token*128 + n] = make_float2(v0, v1);
            }
        }
}

// ---------------- single-pass online column softmax stats ----------------
__global__ void col_stats(const float* __restrict__ S, float* __restrict__ cmax, float* __restrict__ csum)
{
    int gidx = blockIdx.x*256 + threadIdx.x;
    int z = gidx >> 9, ki = gidx & 511;
    const float* col = S + (size_t)z*262144 + ki;
    float m = -1e30f, s = 0.f;
    for (int q = 0; q < 512; q += 16) {
        float v[16];
        #pragma unroll
        for (int i = 0; i < 16; i++) v[i] = col[(size_t)(q+i)*512];
        float lm = v[0];
        #pragma unroll
        for (int i = 1; i < 16; i++) lm = fmaxf(lm, v[i]);
        float nm = fmaxf(m, lm);
        float acc = 0.f;
        #pragma unroll
        for (int i = 0; i < 16; i++) acc += expf(v[i] - nm);
        s = s * expf(m - nm) + acc;
        m = nm;
    }
    cmax[gidx] = m; csum[gidx] = s;
}

// ---------------- PV GEMM (tf32) with prefetch ----------------
__global__ __launch_bounds__(256, 2) void gemm_pv_tf32(
    const float* __restrict__ S, const float* __restrict__ V,
    const float* __restrict__ cmax, const float* __restrict__ csum,
    float* __restrict__ O)
{
    int z = blockIdx.z;
    int m0 = blockIdx.x*128;
    const float* Sz = S + (size_t)z*262144;
    const float* Vz = V + (size_t)z*65536;
    const float* cm = cmax + z*512;
    const float* cs = csum + z*512;
    float* Oz = O + (size_t)z*65536;
    __shared__ float As[16][136], Bs[16][136];
    int tid = threadIdx.x;
    int wid = tid >> 5, lane = tid & 31;
    int g = lane >> 2, tig = lane & 3;
    int wm = (wid >> 1) * 32, wn = (wid & 1) * 64;
    float acc[2][8][4];
    #pragma unroll
    for (int i = 0; i < 2; i++)
        #pragma unroll
        for (int j = 0; j < 8; j++)
            #pragma unroll
            for (int q = 0; q < 4; q++) acc[i][j][q] = 0.f;

    int rowA = tid >> 2, kq = (tid & 3) * 4;
    int n4 = (tid & 31) * 4, kkB = tid >> 5;
    float4 pa[2], pb[2], pcm;
    float pcs[2];
    #pragma unroll
    for (int e = 0; e < 2; e++) {
        pa[e] = *(const float4*)&Sz[(size_t)(m0 + rowA + e*64)*512 + kq];
        pb[e] = *(const float4*)&Vz[(size_t)(kkB + e*8)*128 + n4];
        pcs[e] = cs[kkB + e*8];
    }
    pcm = *(const float4*)&cm[kq];
    for (int k0 = 0; k0 < 512; k0 += 16) {
        #pragma unroll
        for (int e = 0; e < 2; e++) {
            int r = rowA + e*64;
            As[kq+0][r] = tf32r(expf(pa[e].x - pcm.x));
            As[kq+1][r] = tf32r(expf(pa[e].y - pcm.y));
            As[kq+2][r] = tf32r(expf(pa[e].z - pcm.z));
            As[kq+3][r] = tf32r(expf(pa[e].w - pcm.w));
            int kk = kkB + e*8;
            float rs = 1.0f / pcs[e];
            Bs[kk][n4+0] = tf32r(pb[e].x*rs);
            Bs[kk][n4+1] = tf32r(pb[e].y*rs);
            Bs[kk][n4+2] = tf32r(pb[e].z*rs);
            Bs[kk][n4+3] = tf32r(pb[e].w*rs);
        }
        __syncthreads();
        if (k0 + 16 < 512) {
            #pragma unroll
            for (int e = 0; e < 2; e++) {
                pa[e] = *(const float4*)&Sz[(size_t)(m0 + rowA + e*64)*512 + k0 + 16 + kq];
                pb[e] = *(const float4*)&Vz[(size_t)(k0 + 16 + kkB + e*8)*128 + n4];
                pcs[e] = cs[k0 + 16 + kkB + e*8];
            }
            pcm = *(const float4*)&cm[k0 + 16 + kq];
        }
        #pragma unroll
        for (int ks = 0; ks < 16; ks += 8) {
            unsigned af[2][4], bf[8][2];
            #pragma unroll
            for (int mi = 0; mi < 2; mi++) {
                af[mi][0] = __float_as_uint(As[ks+tig  ][wm+mi*16+g  ]);
                af[mi][1] = __float_as_uint(As[ks+tig  ][wm+mi*16+g+8]);
                af[mi][2] = __float_as_uint(As[ks+tig+4][wm+mi*16+g  ]);
                af[mi][3] = __float_as_uint(As[ks+tig+4][wm+mi*16+g+8]);
            }
            #pragma unroll
            for (int ni = 0; ni < 8; ni++) {
                bf[ni][0] = __float_as_uint(Bs[ks+tig  ][wn+ni*8+g]);
                bf[ni][1] = __float_as_uint(Bs[ks+tig+4][wn+ni*8+g]);
            }
            #pragma unroll
            for (int mi = 0; mi < 2; mi++)
                #pragma unroll
                for (int ni = 0; ni < 8; ni++)
                    mma_tf32(acc[mi][ni], af[mi], bf[ni]);
        }
        __syncthreads();
    }
    #pragma unroll
    for (int mi = 0; mi < 2; mi++)
        #pragma unroll
        for (int half = 0; half < 2; half++) {
            int m = m0 + wm + mi*16 + g + half*8;
            #pragma unroll
            for (int ni = 0; ni < 8; ni++) {
                int n = wn + ni*8 + 2*tig;
                *(float2*)&Oz[(size_t)m*128 + n] =
                    make_float2(acc[mi][ni][half*2+0], acc[mi][ni][half*2+1]);
            }
        }
}

// ---------------- FFN stage 1: 4 fused GEMMs off one att tile ----------------
// outputs: xd = gelu(att@div+bd) - gelu(ln1(att)@fc1+b1f)
//          gate = sigmoid(att@act+ba), x3a = gelu(ln3(att)@fc3a+b3a)
__global__ __launch_bounds__(256) void ffn_stage1(
    const float* __restrict__ att,
    const float* __restrict__ fc1w, const float* __restrict__ fc1b,
    const float* __restrict__ divw, const float* __restrict__ divb,
    const float* __restrict__ actw, const float* __restrict__ actb,
    const float* __restrict__ f3aw, const float* __restrict__ f3ab,
    const float* __restrict__ g1, const float* __restrict__ b1,
    const float* __restrict__ g3, const float* __restrict__ b3,
    float* __restrict__ xd, float* __restrict__ gate, float* __restrict__ x3a)
{
    extern __shared__ float sm[];
    float* aT = sm;                 // 128*132
    float* wT = sm + 16896;         // 128*132
    float* lp = sm + 33792;         // g1,b1,g3,b3 (4*128)
    float* meanS = lp + 512;
    float* rstdS = meanS + 128;
    int m0 = blockIdx.x * 128;
    int tid = threadIdx.x;
    {
        int row = tid >> 1, k0 = (tid & 1) * 64;
        const float* src = &att[(size_t)(m0+row)*128 + k0];
        float* dst = &aT[row*132 + k0];
        #pragma unroll
        for (int i = 0; i < 16; i++) *(float4*)&dst[i*4] = *(const float4*)&src[i*4];
    }
    if (tid < 128) { lp[tid]=g1[tid]; lp[128+tid]=b1[tid]; lp[256+tid]=g3[tid]; lp[384+tid]=b3[tid]; }
    __syncthreads();
    {
        int row = tid >> 1, k0 = (tid & 1) * 64;
        float s = 0.f, ss = 0.f;
        #pragma unroll
        for (int i = 0; i < 16; i++) {
            float4 v = *(float4*)&aT[row*132 + k0 + i*4];
            s  += v.x+v.y+v.z+v.w;
            ss += v.x*v.x+v.y*v.y+v.z*v.z+v.w*v.w;
        }
        s  += __shfl_xor_sync(0xffffffffu, s, 1);
        ss += __shfl_xor_sync(0xffffffffu, ss, 1);
        if ((tid & 1) == 0) {
            float mn = s * (1.f/128.f);
            meanS[row] = mn;
            rstdS[row] = rsqrtf(ss*(1.f/128.f) - mn*mn + 1e-5f);
        }
    }
    __syncthreads();
    int wid = tid >> 5, lane = tid & 31, g = lane >> 2, tig = lane & 3;
    int wm = (wid >> 1) * 32, wn = (wid & 1) * 64;
    float mr[4], rr[4];
    #pragma unroll
    for (int mi = 0; mi < 2; mi++)
        #pragma unroll
        for (int h = 0; h < 2; h++) {
            int m = wm + mi*16 + g + h*8;
            mr[mi*2+h] = meanS[m]; rr[mi*2+h] = rstdS[m];
        }
    auto loadW = [&](const float* __restrict__ w) {
        int n = tid >> 1, k0 = (tid & 1) * 64;
        const float* src = &w[n*128 + k0];
        float* dst = &wT[n*132 + k0];
        #pragma unroll
        for (int i = 0; i < 16; i++) {
            float4 v = *(const float4*)&src[i*4];
            dst[i*4+0]=tf32r(v.x); dst[i*4+1]=tf32r(v.y);
            dst[i*4+2]=tf32r(v.z); dst[i*4+3]=tf32r(v.w);
        }
    };
    float a1v[2][8][4], a2v[2][8][4];
    // p0: fc1 with ln1
    loadW(fc1w); __syncthreads();
    mma_pass_k128(aT, wT, wm, wn, g, tig, 1, mr, rr, lp, lp+128, a1v);
    __syncthreads();
    // p1: div raw -> xd
    loadW(divw); __syncthreads();
    mma_pass_k128(aT, wT, wm, wn, g, tig, 0, mr, rr, lp, lp, a2v);
    #pragma unroll
    for (int mi = 0; mi < 2; mi++)
        #pragma unroll
        for (int h = 0; h < 2; h++) {
            int m = m0 + wm + mi*16 + g + h*8;
            #pragma unroll
            for (int ni = 0; ni < 8; ni++) {
                int n = wn + ni*8 + 2*tig;
                float u0 = a1v[mi][ni][h*2+0] + fc1b[n];
                float u1 = a1v[mi][ni][h*2+1] + fc1b[n+1];
                u0 = u0*normcdff(u0); u1 = u1*normcdff(u1);
                float v0 = a2v[mi][ni][h*2+0] + divb[n];
                float v1 = a2v[mi][ni][h*2+1] + divb[n+1];
                v0 = v0*normcdff(v0) - u0; v1 = v1*normcdff(v1) - u1;
                *(float2*)&xd[(size_t)m*128 + n] = make_float2(v0, v1);
            }
        }
    __syncthreads();
    // p2: act raw -> gate
    loadW(actw); __syncthreads();
    mma_pass_k128(aT, wT, wm, wn, g, tig, 0, mr, rr, lp, lp, a2v);
    #pragma unroll
    for (int mi = 0; mi < 2; mi++)
        #pragma unroll
        for (int h = 0; h < 2; h++) {
            int m = m0 + wm + mi*16 + g + h*8;
            #pragma unroll
            for (int ni = 0; ni < 8; ni++) {
                int n = wn + ni*8 + 2*tig;
                float v0 = a2v[mi][ni][h*2+0] + actb[n];
                float v1 = a2v[mi][ni][h*2+1] + actb[n+1];
                v0 = 1.f/(1.f+expf(-v0)); v1 = 1.f/(1.f+expf(-v1));
                *(float2*)&gate[(size_t)m*128 + n] = make_float2(v0, v1);
            }
        }
    __syncthreads();
    // p3: fc3a with ln3 -> x3a
    loadW(f3aw); __syncthreads();
    mma_pass_k128(aT, wT, wm, wn, g, tig, 1, mr, rr, lp+256, lp+384, a2v);
    #pragma unroll
    for (int mi = 0; mi < 2; mi++)
        #pragma unroll
        for (int h = 0; h < 2; h++) {
            int m = m0 + wm + mi*16 + g + h*8;
            #pragma unroll
            for (int ni = 0; ni < 8; ni++) {
                int n = wn + ni*8 + 2*tig;
                float v0 = a2v[mi][ni][h*2+0] + f3ab[n];
                float v1 = a2v[mi][ni][h*2+1] + f3ab[n+1];
                v0 = v0*normcdff(v0); v1 = v1*normcdff(v1);
                *(float2*)&x3a[(size_t)m*128 + n] = make_float2(v0, v1);
            }
        }
}

// ---------------- FFN stage 2: x2=gelu(xd@fc2), x3=x3a@fc3b, ffn=gate*ln(x2+x3) ----------------
__global__ __launch_bounds__(256) void ffn_stage2(
    const float* __restrict__ xd, const float* __restrict__ x3a,
    const float* __restrict__ gate,
    const float* __restrict__ fc2w, const float* __restrict__ fc2b,
    const float* __restrict__ f3bw, const float* __restrict__ f3bb,
    const float* __restrict__ lnng, const float* __restrict__ lnnb,
    float* __restrict__ ffn)
{
    extern __shared__ float sm[];
    float* aT = sm;
    float* wT = sm + 16896;
    float* meanS = sm + 33792;
    float* rstdS = meanS + 128;
    int m0 = blockIdx.x * 128;
    int tid = threadIdx.x;
    int wid = tid >> 5, lane = tid & 31, g = lane >> 2, tig = lane & 3;
    int wm = (wid >> 1) * 32, wn = (wid & 1) * 64;
    auto loadA = [&](const float* __restrict__ A) {
        int row = tid >> 1, k0 = (tid & 1) * 64;
        const float* src = &A[(size_t)(m0+row)*128 + k0];
        float* dst = &aT[row*132 + k0];
        #pragma unroll
        for (int i = 0; i < 16; i++) *(float4*)&dst[i*4] = *(const float4*)&src[i*4];
    };
    auto loadW = [&](const float* __restrict__ w) {
        int n = tid >> 1, k0 = (tid & 1) * 64;
        const float* src = &w[n*128 + k0];
        float* dst = &wT[n*132 + k0];
        #pragma unroll
        for (int i = 0; i < 16; i++) {
            float4 v = *(const float4*)&src[i*4];
            dst[i*4+0]=tf32r(v.x); dst[i*4+1]=tf32r(v.y);
            dst[i*4+2]=tf32r(v.z); dst[i*4+3]=tf32r(v.w);
        }
    };
    float x2v[2][8][4], acc[2][8][4];
    float dummy[4] = {0,0,0,0};
    // pass 1: x2 = gelu(xd@fc2 + b)
    loadA(xd); loadW(fc2w); __syncthreads();
    mma_pass_k128(aT, wT, wm, wn, g, tig, 0, dummy, dummy, meanS, meanS, x2v);
    #pragma unroll
    for (int mi = 0; mi < 2; mi++)
        #pragma unroll
        for (int h = 0; h < 2; h++)
            #pragma unroll
            for (int ni = 0; ni < 8; ni++) {
                int n = wn + ni*8 + 2*tig;
                float v0 = x2v[mi][ni][h*2+0] + fc2b[n];
                float v1 = x2v[mi][ni][h*2+1] + fc2b[n+1];
                x2v[mi][ni][h*2+0] = v0*normcdff(v0);
                x2v[mi][ni][h*2+1] = v1*normcdff(v1);
            }
    __syncthreads();
    // pass 2: x3 = x3a@fc3b + b ; sum in regs
    loadA(x3a); loadW(f3bw); __syncthreads();
    mma_pass_k128(aT, wT, wm, wn, g, tig, 0, dummy, dummy, meanS, meanS, acc);
    __syncthreads();
    // write sums into aT for row stats
    #pragma unroll
    for (int mi = 0; mi < 2; mi++)
        #pragma unroll
        for (int h = 0; h < 2; h++) {
            int ml = wm + mi*16 + g + h*8;
            #pragma unroll
            for (int ni = 0; ni < 8; ni++) {
                int n = wn + ni*8 + 2*tig;
                float s0 = x2v[mi][ni][h*2+0] + acc[mi][ni][h*2+0] + f3bb[n];
                float s1 = x2v[mi][ni][h*2+1] + acc[mi][ni][h*2+1] + f3bb[n+1];
                acc[mi][ni][h*2+0] = s0; acc[mi][ni][h*2+1] = s1;
                aT[ml*132 + n] = s0; aT[ml*132 + n + 1] = s1;
            }
        }
    __syncthreads();
    {
        int row = tid >> 1, k0 = (tid & 1) * 64;
        float s = 0.f, ss = 0.f;
        #pragma unroll
        for (int i = 0; i < 16; i++) {
            float4 v = *(float4*)&aT[row*132 + k0 + i*4];
            s  += v.x+v.y+v.z+v.w;
            ss += v.x*v.x+v.y*v.y+v.z*v.z+v.w*v.w;
        }
        s  += __shfl_xor_sync(0xffffffffu, s, 1);
        ss += __shfl_xor_sync(0xffffffffu, ss, 1);
        if ((tid & 1) == 0) {
            float mn = s * (1.f/128.f);
            meanS[row] = mn;
            rstdS[row] = rsqrtf(ss*(1.f/128.f) - mn*mn + 1e-5f);
        }
    }
    __syncthreads();
    #pragma unroll
    for (int mi = 0; mi < 2; mi++)
        #pragma unroll
        for (int h = 0; h < 2; h++) {
            int ml = wm + mi*16 + g + h*8;
            int m = m0 + ml;
            float mn = meanS[ml], rs = rstdS[ml];
            #pragma unroll
            for (int ni = 0; ni < 8; ni++) {
                int n = wn + ni*8 + 2*tig;
                float2 gt = *(const float2*)&gate[(size_t)m*128 + n];
                float v0 = ((acc[mi][ni][h*2+0]-mn)*rs*lnng[n]   + lnnb[n])   * gt.x;
                float v1 = ((acc[mi][ni][h*2+1]-mn)*rs*lnng[n+1] + lnnb[n+1]) * gt.y;
                *(float2*)&ffn[(size_t)m*128 + n] = make_float2(v0, v1);
            }
        }
}

// ---------------- final combine ----------------
__global__ void final_kernel(const float* __restrict__ x, const float* __restrict__ ffn,
                             const float* __restrict__ yt, const float* __restrict__ dwb,
                             float* __restrict__ out)
{
    int oh = blockIdx.x;
    int cq = blockIdx.y;
    int b  = blockIdx.z;
    int c0 = cq*32;
    __shared__ float s_f[64*33], s_y[64*33], s_d[64*33];
    int tid = threadIdx.x;
    size_t tok0 = (size_t)b*4096 + (size_t)oh*64;
    #pragma unroll
    for (int k = 0; k < 8; k++) {
        int e = tid + k*256;
        int cl = e & 31, t = e >> 5;
        size_t ga = (tok0 + t)*128 + c0 + cl;
        s_f[t*33+cl] = ffn[ga];
        s_y[t*33+cl] = yt[ga];
        s_d[t*33+cl] = dwb[ga];
    }
    float ph = (float)oh * (127.0f/63.0f);
    int y0 = min((int)floorf(ph), 127);
    int y1 = min(y0+1, 127);
    float wy = ph - (float)y0;
    __syncthreads();
    #pragma unroll
    for (int k = 0; k < 8; k++) {
        int e = tid + k*256;
        int ow = e & 63, cl = e >> 6;
        float pw = (float)ow * (127.0f/63.0f);
        int x0 = min((int)floorf(pw), 127);
        int x1 = min(x0+1, 127);
        float wx = pw - (float)x0;
        const float* xr = x + (((size_t)b*128 + c0 + cl)*128)*128;
        float r0 = xr[(size_t)y0*128 + x0]*(1.f-wx) + xr[(size_t)y0*128 + x1]*wx;
        float r1 = xr[(size_t)y1*128 + x0]*(1.f-wx) + xr[(size_t)y1*128 + x1]*wx;
        float down = r0*(1.f-wy) + r1*wy;
        float v = s_f[ow*33+cl]*(down - s_d[ow*33+cl]) + s_y[ow*33+cl];
        out[(((size_t)b*128 + c0+cl)*64 + oh)*64 + ow] = v;
    }
}

extern "C" void kernel_launch(void* const* d_in, const int* in_sizes, int n_in,
                              void* d_out, int out_size)
{
    (void)in_sizes; (void)n_in; (void)out_size;
    const float* x      = (const float*)d_in[0];
    const float* conv1w = (const float*)d_in[1];
    const float* conv1b = (const float*)d_in[2];
    const float* l1w    = (const float*)d_in[3];
    const float* l1b    = (const float*)d_in[4];
    const float* ln1g   = (const float*)d_in[5];
    const float* ln1b   = (const float*)d_in[6];
    const float* fc1w   = (const float*)d_in[7];
    const float* fc1b   = (const float*)d_in[8];
    const float* divw   = (const float*)d_in[9];
    const float* divb   = (const float*)d_in[10];
    const float* fc2w   = (const float*)d_in[11];
    const float* fc2b   = (const float*)d_in[12];
    const float* ln3g   = (const float*)d_in[13];
    const float* ln3b   = (const float*)d_in[14];
    const float* fc3aw  = (const float*)d_in[15];
    const float* fc3ab  = (const float*)d_in[16];
    const float* fc3bw  = (const float*)d_in[17];
    const float* fc3bb  = (const float*)d_in[18];
    const float* lnng   = (const float*)d_in[19];
    const float* lnnb   = (const float*)d_in[20];
    const float* actw   = (const float*)d_in[21];
    const float* actb   = (const float*)d_in[22];
    float* out = (float*)d_out;

    float* pool = nullptr;
    cudaGetSymbolAddress((void**)&pool, g_pool);

    float* yL   = pool + 0*U;
    float* yHH  = pool + 1*U;
    float* hllh = pool + 2*U;   // 2U
    float* y    = pool + 4*U;
    float* S    = pool + 5*U;   // 5U..9U
    float* att  = pool + 2*U;   // reuse hllh lo
    float* xd   = pool + 3*U;   // reuse hllh hi
    float* x3a  = pool + 5*U;   // reuse S (dead after PV)
    float* gate = pool + 0*U;   // reuse yL (dead after QK)
    float* ffn  = pool + 1*U;   // reuse yHH (dead after PV)
    float* dw   = pool + 10*U;
    float* cmax = pool + 11*U;
    float* csum = pool + 11*U + 65536;

    static const int SMEM1 = (2*16896 + 512 + 256) * 4;
    static const int SMEM2 = (2*16896 + 256) * 4;
    cudaFuncSetAttribute(ffn_stage1, cudaFuncAttributeMaxDynamicSharedMemorySize, SMEM1);
    cudaFuncSetAttribute(ffn_stage2, cudaFuncAttributeMaxDynamicSharedMemorySize, SMEM2);

    // 1. DWT
    dwt_kernel<<<dim3(64,8,16), 256>>>(x, hllh, yL, yHH);
    // 2. conv1 (1x1 as GEMM)
    gemm_tf32<<<dim3(512,1,1), 256>>>(hllh, 0, 256, conv1w, 0, 256,
                                      y, 0, 128, 256, 1.0f, conv1b, 0, nullptr);
    // 3. S = Q K^T * 8^-0.5
    gemm_tf32<<<dim3(4,4,128), 256>>>(yL, 65536, 128, y, 65536, 128,
                                      S, 262144, 512, 128, 0.35355339059327f, nullptr, 0, nullptr);
    // 4. column softmax stats
    col_stats<<<256, 256>>>(S, cmax, csum);
    // 5. att = P @ V
    gemm_pv_tf32<<<dim3(4,1,128), 256>>>(S, yHH, cmax, csum, att);
    // 6. FFN stage 1 (fc1/div/act/fc3a + ln1/ln3 fused)
    ffn_stage1<<<512, 256, SMEM1>>>(att, fc1w, fc1b, divw, divb, actw, actb,
                                    fc3aw, fc3ab, ln1g, ln1b, ln3g, ln3b,
                                    xd, gate, x3a);
    // 7. FFN stage 2 (fc2/fc3b + lnn + gate fused)
    ffn_stage2<<<512, 256, SMEM2>>>(xd, x3a, gate, fc2w, fc2b, fc3bw, fc3bb,
                                    lnng, lnnb, ffn);
    // 8. fused implicit-GEMM l1 conv
    conv_l1_tf32<<<dim3(32,1,16), 256>>>(x, l1w, l1b, dw);
    // 9. combine
    final_kernel<<<dim3(64,4,16), 256>>>(x, ffn, y, dw, out);
}

// round 13
// speedup vs baseline: 1.1002x; 1.1002x over previous
#include <cuda_runtime.h>
#include <math.h>

#define U 8388608UL
__device__ __align__(256) float g_pool[11*U + 262144];

// ---------------- helpers ----------------
__device__ __forceinline__ float tf32r(float v) {
    unsigned u;
    asm("cvt.rna.tf32.f32 %0, %1;" : "=r"(u) : "f"(v));
    return __uint_as_float(u);
}
__device__ __forceinline__ void mma_tf32(float* c, const unsigned* a, const unsigned* b) {
    asm volatile(
        "mma.sync.aligned.m16n8k8.row.col.f32.tf32.tf32.f32 "
        "{%0,%1,%2,%3},{%4,%5,%6,%7},{%8,%9},{%0,%1,%2,%3};"
        : "+f"(c[0]), "+f"(c[1]), "+f"(c[2]), "+f"(c[3])
        : "r"(a[0]), "r"(a[1]), "r"(a[2]), "r"(a[3]), "r"(b[0]), "r"(b[1]));
}

// ---------------- DWT ----------------
__global__ void dwt_kernel(const float* __restrict__ x, float* __restrict__ hllh,
                           float* __restrict__ yL, float* __restrict__ yHH)
{
    int i  = blockIdx.x;
    int cb = blockIdx.y;
    int b  = blockIdx.z;
    __shared__ float s[16][2][129];
    int tid = threadIdx.x;
    #pragma unroll
    for (int k = 0; k < 16; k++) {
        int e = tid + k*256;
        int cc = e >> 8, r = (e >> 7) & 1, col = e & 127;
        s[cc][r][col] = x[(((size_t)(b*128 + cb*16 + cc))*128 + 2*i + r)*128 + col];
    }
    __syncthreads();
    #pragma unroll
    for (int k = 0; k < 4; k++) {
        int e = tid + k*256;
        int cc = e & 15, j = e >> 4;
        float a  = s[cc][0][2*j], bb = s[cc][0][2*j+1];
        float c_ = s[cc][1][2*j], d  = s[cc][1][2*j+1];
        size_t token = (size_t)b*4096 + (size_t)i*64 + j;
        int c = cb*16 + cc;
        yL [token*128 + c]        = (a+bb+c_+d)*0.5f;
        yHH[token*128 + c]        = (a-bb-c_+d)*0.5f;
        hllh[token*256 + c]       = (a-bb+c_-d)*0.5f;
        hllh[token*256 + 128 + c] = (a+bb-c_-d)*0.5f;
    }
}

// ---------------- per-token LN stats (warp per token) ----------------
__global__ void ln_stats(const float* __restrict__ X, float* __restrict__ tm, float* __restrict__ tr)
{
    int wrp = threadIdx.x >> 5, lane = threadIdx.x & 31;
    size_t token = (size_t)blockIdx.x*8 + wrp;
    const float4 v = *(const float4*)&X[token*128 + lane*4];
    float s  = v.x+v.y+v.z+v.w;
    float ss = v.x*v.x+v.y*v.y+v.z*v.z+v.w*v.w;
    #pragma unroll
    for (int o = 16; o; o >>= 1) {
        s  += __shfl_xor_sync(0xffffffffu, s,  o);
        ss += __shfl_xor_sync(0xffffffffu, ss, o);
    }
    if (lane == 0) {
        float mean = s * (1.f/128.f);
        tm[token] = mean;
        tr[token] = rsqrtf(ss*(1.f/128.f) - mean*mean + 1e-5f);
    }
}

// ---------------- tf32 NT GEMM with register prefetch + optional LN on A ----------------
// C = epi(scale*LN(A).B^T + bias) - aux ; epi: 0 none, 1 gelu, 2 sigmoid
__global__ __launch_bounds__(256, 2) void gemm_tf32(
    const float* __restrict__ A, size_t sAz, int lda,
    const float* __restrict__ B, size_t sBz, int ldb,
    float* __restrict__ C, size_t sCz, int ldc,
    int K, float scale, const float* __restrict__ bias,
    int epi, const float* __restrict__ aux,
    const float* __restrict__ lnm, const float* __restrict__ lnr,
    const float* __restrict__ lng, const float* __restrict__ lnb)
{
    const float* Ab = A + (size_t)blockIdx.z * sAz;
    const float* Bb = B + (size_t)blockIdx.z * sBz;
    float* Cb = C + (size_t)blockIdx.z * sCz;
    int m0 = blockIdx.x * 128, n0 = blockIdx.y * 128;
    __shared__ float As[16][136], Bs[16][136];
    int tid = threadIdx.x;
    int wid = tid >> 5, lane = tid & 31;
    int g = lane >> 2, tig = lane & 3;
    int wm = (wid >> 1) * 32, wn = (wid & 1) * 64;
    float acc[2][8][4];
    #pragma unroll
    for (int i = 0; i < 2; i++)
        #pragma unroll
        for (int j = 0; j < 8; j++)
            #pragma unroll
            for (int q = 0; q < 4; q++) acc[i][j][q] = 0.f;

    int rowA = tid >> 2, kq = (tid & 3) * 4;
    float mrow[2] = {0.f, 0.f}, rrow[2] = {1.f, 1.f};
    if (lnm) {
        #pragma unroll
        for (int e = 0; e < 2; e++) {
            mrow[e] = lnm[m0 + rowA + e*64];
            rrow[e] = lnr[m0 + rowA + e*64];
        }
    }
    float4 pa[2], pb[2];
    #pragma unroll
    for (int e = 0; e < 2; e++) {
        int r = rowA + e*64;
        pa[e] = *(const float4*)&Ab[(size_t)(m0 + r)*lda + kq];
        pb[e] = *(const float4*)&Bb[(size_t)(n0 + r)*ldb + kq];
    }
    for (int k0 = 0; k0 < K; k0 += 16) {
        if (lnm) {
            float4 gk = *(const float4*)&lng[k0 + kq];
            float4 bk = *(const float4*)&lnb[k0 + kq];
            #pragma unroll
            for (int e = 0; e < 2; e++) {
                int r = rowA + e*64;
                As[kq+0][r]=tf32r(fmaf((pa[e].x-mrow[e])*rrow[e], gk.x, bk.x));
                As[kq+1][r]=tf32r(fmaf((pa[e].y-mrow[e])*rrow[e], gk.y, bk.y));
                As[kq+2][r]=tf32r(fmaf((pa[e].z-mrow[e])*rrow[e], gk.z, bk.z));
                As[kq+3][r]=tf32r(fmaf((pa[e].w-mrow[e])*rrow[e], gk.w, bk.w));
                Bs[kq+0][r]=tf32r(pb[e].x); Bs[kq+1][r]=tf32r(pb[e].y);
                Bs[kq+2][r]=tf32r(pb[e].z); Bs[kq+3][r]=tf32r(pb[e].w);
            }
        } else {
            #pragma unroll
            for (int e = 0; e < 2; e++) {
                int r = rowA + e*64;
                As[kq+0][r]=tf32r(pa[e].x); As[kq+1][r]=tf32r(pa[e].y);
                As[kq+2][r]=tf32r(pa[e].z); As[kq+3][r]=tf32r(pa[e].w);
                Bs[kq+0][r]=tf32r(pb[e].x); Bs[kq+1][r]=tf32r(pb[e].y);
                Bs[kq+2][r]=tf32r(pb[e].z); Bs[kq+3][r]=tf32r(pb[e].w);
            }
        }
        __syncthreads();
        if (k0 + 16 < K) {
            #pragma unroll
            for (int e = 0; e < 2; e++) {
                int r = rowA + e*64;
                pa[e] = *(const float4*)&Ab[(size_t)(m0 + r)*lda + k0 + 16 + kq];
                pb[e] = *(const float4*)&Bb[(size_t)(n0 + r)*ldb + k0 + 16 + kq];
            }
        }
        #pragma unroll
        for (int ks = 0; ks < 16; ks += 8) {
            unsigned af[2][4], bf[8][2];
            #pragma unroll
            for (int mi = 0; mi < 2; mi++) {
                af[mi][0] = __float_as_uint(As[ks+tig  ][wm+mi*16+g  ]);
                af[mi][1] = __float_as_uint(As[ks+tig  ][wm+mi*16+g+8]);
                af[mi][2] = __float_as_uint(As[ks+tig+4][wm+mi*16+g  ]);
                af[mi][3] = __float_as_uint(As[ks+tig+4][wm+mi*16+g+8]);
            }
            #pragma unroll
            for (int ni = 0; ni < 8; ni++) {
                bf[ni][0] = __float_as_uint(Bs[ks+tig  ][wn+ni*8+g]);
                bf[ni][1] = __float_as_uint(Bs[ks+tig+4][wn+ni*8+g]);
            }
            #pragma unroll
            for (int mi = 0; mi < 2; mi++)
                #pragma unroll
                for (int ni = 0; ni < 8; ni++)
                    mma_tf32(acc[mi][ni], af[mi], bf[ni]);
        }
        __syncthreads();
    }
    #pragma unroll
    for (int mi = 0; mi < 2; mi++)
        #pragma unroll
        for (int half = 0; half < 2; half++) {
            int m = m0 + wm + mi*16 + g + half*8;
            #pragma unroll
            for (int ni = 0; ni < 8; ni++) {
                int n = n0 + wn + ni*8 + 2*tig;
                float v0 = acc[mi][ni][half*2+0]*scale;
                float v1 = acc[mi][ni][half*2+1]*scale;
                if (bias) { v0 += bias[n]; v1 += bias[n+1]; }
                if (epi == 1) { v0 = v0*normcdff(v0); v1 = v1*normcdff(v1); }
                else if (epi == 2) { v0 = 1.f/(1.f+expf(-v0)); v1 = 1.f/(1.f+expf(-v1)); }
                if (aux) { v0 -= aux[(size_t)m*ldc+n]; v1 -= aux[(size_t)m*ldc+n+1]; }
                *(float2*)&Cb[(size_t)m*ldc + n] = make_float2(v0, v1);
            }
        }
}

// ---------------- fused implicit-GEMM l1 conv (4x4, s2, p1, relu) ----------------
__global__ __launch_bounds__(256, 2) void conv_l1_tf32(
    const float* __restrict__ x, const float* __restrict__ w,
    const float* __restrict__ bias, float* __restrict__ dw)
{
    int blk = blockIdx.x;
    int b   = blockIdx.z;
    int oh0 = blk*2;
    __shared__ float patch[8][6][132];
    __shared__ float As[16][136], Bs[16][136];
    int tid = threadIdx.x;
    int wid = tid >> 5, lane = tid & 31;
    int g = lane >> 2, tig = lane & 3;
    int wm = (wid >> 1) * 32, wn = (wid & 1) * 64;
    float acc[2][8][4];
    #pragma unroll
    for (int i = 0; i < 2; i++)
        #pragma unroll
        for (int j = 0; j < 8; j++)
            #pragma unroll
            for (int q = 0; q < 4; q++) acc[i][j][q] = 0.f;

    int t = tid & 127, kkq = (tid >> 7) * 8;
    int ohl = t >> 6, ow = t & 63;
    int coB = tid >> 1, kbB = (tid & 1) * 8;

    for (int ci0 = 0; ci0 < 128; ci0 += 8) {
        for (int e = tid; e < 8*6*130; e += 256) {
            int cil = e / 780;
            int rem = e - cil*780;
            int r = rem / 130, cc = rem - r*130;
            int gr = 2*oh0 - 1 + r, gc = cc - 1;
            float v = 0.f;
            if ((unsigned)gr < 128u && (unsigned)gc < 128u)
                v = x[(((size_t)b*128 + ci0 + cil)*128 + gr)*128 + gc];
            patch[cil][r][cc] = tf32r(v);
        }
        __syncthreads();
        #pragma unroll 1
        for (int cil = 0; cil < 8; cil++) {
            int kbase = (ci0 + cil) * 16;
            #pragma unroll
            for (int i = 0; i < 8; i++) {
                int kk = kkq + i;
                int kh = kk >> 2, kw = kk & 3;
                As[kk][t] = patch[cil][2*ohl + kh][2*ow + kw];
            }
            {
                float4 w0 = *(const float4*)&w[(size_t)coB*2048 + kbase + kbB];
                float4 w1 = *(const float4*)&w[(size_t)coB*2048 + kbase + kbB + 4];
                Bs[kbB+0][coB]=tf32r(w0.x); Bs[kbB+1][coB]=tf32r(w0.y);
                Bs[kbB+2][coB]=tf32r(w0.z); Bs[kbB+3][coB]=tf32r(w0.w);
                Bs[kbB+4][coB]=tf32r(w1.x); Bs[kbB+5][coB]=tf32r(w1.y);
                Bs[kbB+6][coB]=tf32r(w1.z); Bs[kbB+7][coB]=tf32r(w1.w);
            }
            __syncthreads();
            #pragma unroll
            for (int ks = 0; ks < 16; ks += 8) {
                unsigned af[2][4], bf[8][2];
                #pragma unroll
                for (int mi = 0; mi < 2; mi++) {
                    af[mi][0] = __float_as_uint(As[ks+tig  ][wm+mi*16+g  ]);
                    af[mi][1] = __float_as_uint(As[ks+tig  ][wm+mi*16+g+8]);
                    af[mi][2] = __float_as_uint(As[ks+tig+4][wm+mi*16+g  ]);
                    af[mi][3] = __float_as_uint(As[ks+tig+4][wm+mi*16+g+8]);
                }
                #pragma unroll
                for (int ni = 0; ni < 8; ni++) {
                    bf[ni][0] = __float_as_uint(Bs[ks+tig  ][wn+ni*8+g]);
                    bf[ni][1] = __float_as_uint(Bs[ks+tig+4][wn+ni*8+g]);
                }
                #pragma unroll
                for (int mi = 0; mi < 2; mi++)
                    #pragma unroll
                    for (int ni = 0; ni < 8; ni++)
                        mma_tf32(acc[mi][ni], af[mi], bf[ni]);
            }
            __syncthreads();
        }
    }
    #pragma unroll
    for (int mi = 0; mi < 2; mi++)
        #pragma unroll
        for (int half = 0; half < 2; half++) {
            int midx = wm + mi*16 + g + half*8;
            size_t token = (size_t)b*4096 + (size_t)blk*128 + midx;
            #pragma unroll
            for (int ni = 0; ni < 8; ni++) {
                int n = wn + ni*8 + 2*tig;
                float v0 = fmaxf(acc[mi][ni][half*2+0] + bias[n],   0.f);
                float v1 = fmaxf(acc[mi][ni][half*2+1] + bias[n+1], 0.f);
                *(float2*)&dw[token*128 + n] = make_float2(v0, v1);
            }
        }
}

// ---------------- column softmax stats, 4 threads per column ----------------
__global__ void col_stats(const float* __restrict__ S, float* __restrict__ cmax, float* __restrict__ csum)
{
    int gidx = blockIdx.x*256 + threadIdx.x;   // 262144 threads
    int col = gidx >> 2, tq = gidx & 3;
    int z = col >> 9, ki = col & 511;
    const float* base = S + (size_t)z*262144 + ki + (size_t)tq*128*512;
    float m = -1e30f, s = 0.f;
    for (int q = 0; q < 128; q += 8) {
        float v[8];
        #pragma unroll
        for (int i = 0; i < 8; i++) v[i] = base[(size_t)(q+i)*512];
        float lm = v[0];
        #pragma unroll
        for (int i = 1; i < 8; i++) lm = fmaxf(lm, v[i]);
        float nm = fmaxf(m, lm);
        float acc = 0.f;
        #pragma unroll
        for (int i = 0; i < 8; i++) acc += expf(v[i] - nm);
        s = s * expf(m - nm) + acc;
        m = nm;
    }
    #pragma unroll
    for (int off = 1; off < 4; off <<= 1) {
        float om = __shfl_xor_sync(0xffffffffu, m, off);
        float os = __shfl_xor_sync(0xffffffffu, s, off);
        float nm = fmaxf(m, om);
        s = s*expf(m - nm) + os*expf(om - nm);
        m = nm;
    }
    if (tq == 0) { cmax[col] = m; csum[col] = s; }
}

// ---------------- PV GEMM (tf32) with prefetch ----------------
__global__ __launch_bounds__(256, 2) void gemm_pv_tf32(
    const float* __restrict__ S, const float* __restrict__ V,
    const float* __restrict__ cmax, const float* __restrict__ csum,
    float* __restrict__ O)
{
    int z = blockIdx.z;
    int m0 = blockIdx.x*128;
    const float* Sz = S + (size_t)z*262144;
    const float* Vz = V + (size_t)z*65536;
    const float* cm = cmax + z*512;
    const float* cs = csum + z*512;
    float* Oz = O + (size_t)z*65536;
    __shared__ float As[16][136], Bs[16][136];
    int tid = threadIdx.x;
    int wid = tid >> 5, lane = tid & 31;
    int g = lane >> 2, tig = lane & 3;
    int wm = (wid >> 1) * 32, wn = (wid & 1) * 64;
    float acc[2][8][4];
    #pragma unroll
    for (int i = 0; i < 2; i++)
        #pragma unroll
        for (int j = 0; j < 8; j++)
            #pragma unroll
            for (int q = 0; q < 4; q++) acc[i][j][q] = 0.f;

    int rowA = tid >> 2, kq = (tid & 3) * 4;
    int n4 = (tid & 31) * 4, kkB = tid >> 5;
    float4 pa[2], pb[2], pcm;
    float pcs[2];
    #pragma unroll
    for (int e = 0; e < 2; e++) {
        pa[e] = *(const float4*)&Sz[(size_t)(m0 + rowA + e*64)*512 + kq];
        pb[e] = *(const float4*)&Vz[(size_t)(kkB + e*8)*128 + n4];
        pcs[e] = cs[kkB + e*8];
    }
    pcm = *(const float4*)&cm[kq];
    for (int k0 = 0; k0 < 512; k0 += 16) {
        #pragma unroll
        for (int e = 0; e < 2; e++) {
            int r = rowA + e*64;
            As[kq+0][r] = tf32r(expf(pa[e].x - pcm.x));
            As[kq+1][r] = tf32r(expf(pa[e].y - pcm.y));
            As[kq+2][r] = tf32r(expf(pa[e].z - pcm.z));
            As[kq+3][r] = tf32r(expf(pa[e].w - pcm.w));
            int kk = kkB + e*8;
            float rs = 1.0f / pcs[e];
            Bs[kk][n4+0] = tf32r(pb[e].x*rs);
            Bs[kk][n4+1] = tf32r(pb[e].y*rs);
            Bs[kk][n4+2] = tf32r(pb[e].z*rs);
            Bs[kk][n4+3] = tf32r(pb[e].w*rs);
        }
        __syncthreads();
        if (k0 + 16 < 512) {
            #pragma unroll
            for (int e = 0; e < 2; e++) {
                pa[e] = *(const float4*)&Sz[(size_t)(m0 + rowA + e*64)*512 + k0 + 16 + kq];
                pb[e] = *(const float4*)&Vz[(size_t)(k0 + 16 + kkB + e*8)*128 + n4];
                pcs[e] = cs[k0 + 16 + kkB + e*8];
            }
            pcm = *(const float4*)&cm[k0 + 16 + kq];
        }
        #pragma unroll
        for (int ks = 0; ks < 16; ks += 8) {
            unsigned af[2][4], bf[8][2];
            #pragma unroll
            for (int mi = 0; mi < 2; mi++) {
                af[mi][0] = __float_as_uint(As[ks+tig  ][wm+mi*16+g  ]);
                af[mi][1] = __float_as_uint(As[ks+tig  ][wm+mi*16+g+8]);
                af[mi][2] = __float_as_uint(As[ks+tig+4][wm+mi*16+g  ]);
                af[mi][3] = __float_as_uint(As[ks+tig+4][wm+mi*16+g+8]);
            }
            #pragma unroll
            for (int ni = 0; ni < 8; ni++) {
                bf[ni][0] = __float_as_uint(Bs[ks+tig  ][wn+ni*8+g]);
                bf[ni][1] = __float_as_uint(Bs[ks+tig+4][wn+ni*8+g]);
            }
            #pragma unroll
            for (int mi = 0; mi < 2; mi++)
                #pragma unroll
                for (int ni = 0; ni < 8; ni++)
                    mma_tf32(acc[mi][ni], af[mi], bf[ni]);
        }
        __syncthreads();
    }
    #pragma unroll
    for (int mi = 0; mi < 2; mi++)
        #pragma unroll
        for (int half = 0; half < 2; half++) {
            int m = m0 + wm + mi*16 + g + half*8;
            #pragma unroll
            for (int ni = 0; ni < 8; ni++) {
                int n = wn + ni*8 + 2*tig;
                *(float2*)&Oz[(size_t)m*128 + n] =
                    make_float2(acc[mi][ni][half*2+0], acc[mi][ni][half*2+1]);
            }
        }
}

// ---------------- out = gate * ln(x2+x3) ----------------
__global__ void ln_final(const float* __restrict__ X2, const float* __restrict__ X3,
                         const float* __restrict__ G, const float* __restrict__ gv,
                         const float* __restrict__ bv, float* __restrict__ out)
{
    int wrp = threadIdx.x >> 5, lane = threadIdx.x & 31;
    size_t token = (size_t)blockIdx.x*8 + wrp;
    float4 a = *(const float4*)&X2[token*128 + lane*4];
    float4 c = *(const float4*)&X3[token*128 + lane*4];
    float4 v = make_float4(a.x+c.x, a.y+c.y, a.z+c.z, a.w+c.w);
    float s  = v.x+v.y+v.z+v.w;
    float ss = v.x*v.x+v.y*v.y+v.z*v.z+v.w*v.w;
    #pragma unroll
    for (int o = 16; o; o >>= 1) {
        s  += __shfl_xor_sync(0xffffffffu, s,  o);
        ss += __shfl_xor_sync(0xffffffffu, ss, o);
    }
    float mean = s * (1.f/128.f);
    float rstd = rsqrtf(ss*(1.f/128.f) - mean*mean + 1e-5f);
    float4 g = *(const float4*)&gv[lane*4];
    float4 b = *(const float4*)&bv[lane*4];
    float4 gt = *(const float4*)&G[token*128 + lane*4];
    float4 o;
    o.x = gt.x * ((v.x-mean)*rstd*g.x + b.x);
    o.y = gt.y * ((v.y-mean)*rstd*g.y + b.y);
    o.z = gt.z * ((v.z-mean)*rstd*g.z + b.z);
    o.w = gt.w * ((v.w-mean)*rstd*g.w + b.w);
    *(float4*)&out[token*128 + lane*4] = o;
}

// ---------------- final combine ----------------
__global__ void final_kernel(const float* __restrict__ x, const float* __restrict__ ffn,
                             const float* __restrict__ yt, const float* __restrict__ dwb,
                             float* __restrict__ out)
{
    int oh = blockIdx.x;
    int cq = blockIdx.y;
    int b  = blockIdx.z;
    int c0 = cq*32;
    __shared__ float s_f[64*33], s_y[64*33], s_d[64*33];
    int tid = threadIdx.x;
    size_t tok0 = (size_t)b*4096 + (size_t)oh*64;
    #pragma unroll
    for (int k = 0; k < 8; k++) {
        int e = tid + k*256;
        int cl = e & 31, t = e >> 5;
        size_t ga = (tok0 + t)*128 + c0 + cl;
        s_f[t*33+cl] = ffn[ga];
        s_y[t*33+cl] = yt[ga];
        s_d[t*33+cl] = dwb[ga];
    }
    float ph = (float)oh * (127.0f/63.0f);
    int y0 = min((int)floorf(ph), 127);
    int y1 = min(y0+1, 127);
    float wy = ph - (float)y0;
    __syncthreads();
    #pragma unroll
    for (int k = 0; k < 8; k++) {
        int e = tid + k*256;
        int ow = e & 63, cl = e >> 6;
        float pw = (float)ow * (127.0f/63.0f);
        int x0 = min((int)floorf(pw), 127);
        int x1 = min(x0+1, 127);
        float wx = pw - (float)x0;
        const float* xr = x + (((size_t)b*128 + c0 + cl)*128)*128;
        float r0 = xr[(size_t)y0*128 + x0]*(1.f-wx) + xr[(size_t)y0*128 + x1]*wx;
        float r1 = xr[(size_t)y1*128 + x0]*(1.f-wx) + xr[(size_t)y1*128 + x1]*wx;
        float down = r0*(1.f-wy) + r1*wy;
        float v = s_f[ow*33+cl]*(down - s_d[ow*33+cl]) + s_y[ow*33+cl];
        out[(((size_t)b*128 + c0+cl)*64 + oh)*64 + ow] = v;
    }
}

extern "C" void kernel_launch(void* const* d_in, const int* in_sizes, int n_in,
                              void* d_out, int out_size)
{
    (void)in_sizes; (void)n_in; (void)out_size;
    const float* x      = (const float*)d_in[0];
    const float* conv1w = (const float*)d_in[1];
    const float* conv1b = (const float*)d_in[2];
    const float* l1w    = (const float*)d_in[3];
    const float* l1b    = (const float*)d_in[4];
    const float* ln1g   = (const float*)d_in[5];
    const float* ln1b   = (const float*)d_in[6];
    const float* fc1w   = (const float*)d_in[7];
    const float* fc1b   = (const float*)d_in[8];
    const float* divw   = (const float*)d_in[9];
    const float* divb   = (const float*)d_in[10];
    const float* fc2w   = (const float*)d_in[11];
    const float* fc2b   = (const float*)d_in[12];
    const float* ln3g   = (const float*)d_in[13];
    const float* ln3b   = (const float*)d_in[14];
    const float* fc3aw  = (const float*)d_in[15];
    const float* fc3ab  = (const float*)d_in[16];
    const float* fc3bw  = (const float*)d_in[17];
    const float* fc3bb  = (const float*)d_in[18];
    const float* lnng   = (const float*)d_in[19];
    const float* lnnb   = (const float*)d_in[20];
    const float* actw   = (const float*)d_in[21];
    const float* actb   = (const float*)d_in[22];
    float* out = (float*)d_out;

    float* pool = nullptr;
    cudaGetSymbolAddress((void**)&pool, g_pool);

    float* yL    = pool + 0*U;
    float* yHH   = pool + 1*U;
    float* hllh  = pool + 2*U;   // 2U..4U
    float* y     = pool + 4*U;
    float* S     = pool + 5*U;   // 5U..9U
    float* att   = pool + 2*U;   // reuse hllh lo
    float* xd    = pool + 3*U;   // reuse hllh hi
    float* x1    = pool + 9*U;
    float* x2    = pool + 5*U;   // reuse S (dead after PV)
    float* x3a   = pool + 6*U;
    float* x3    = pool + 7*U;
    float* gate  = pool + 0*U;   // reuse yL
    float* ffn   = pool + 1*U;   // reuse yHH
    float* dw    = pool + 10*U;
    float* cmax  = pool + 11*U;
    float* csum  = pool + 11*U + 65536;
    float* tmean = pool + 11*U + 131072;
    float* trstd = pool + 11*U + 196608;

    // 1. DWT
    dwt_kernel<<<dim3(64,8,16), 256>>>(x, hllh, yL, yHH);
    // 2. conv1 (1x1 as GEMM)
    gemm_tf32<<<dim3(512,1,1), 256>>>(hllh, 0, 256, conv1w, 0, 256,
                                      y, 0, 128, 256, 1.0f, conv1b, 0, nullptr,
                                      nullptr, nullptr, nullptr, nullptr);
    // 3. S = Q K^T * 8^-0.5
    gemm_tf32<<<dim3(4,4,128), 256>>>(yL, 65536, 128, y, 65536, 128,
                                      S, 262144, 512, 128, 0.35355339059327f, nullptr, 0, nullptr,
                                      nullptr, nullptr, nullptr, nullptr);
    // 4. column softmax stats (4-way)
    col_stats<<<1024, 256>>>(S, cmax, csum);
    // 5. att = P @ V
    gemm_pv_tf32<<<dim3(4,1,128), 256>>>(S, yHH, cmax, csum, att);
    // 6. token LN stats of att
    ln_stats<<<8192, 256>>>(att, tmean, trstd);
    // 7. FFN GEMMs (ln1/ln3 folded into A-load)
    gemm_tf32<<<dim3(512,1,1), 256>>>(att, 0, 128, fc1w, 0, 128, x1, 0, 128, 128, 1.f, fc1b, 1, nullptr,
                                      tmean, trstd, ln1g, ln1b);
    gemm_tf32<<<dim3(512,1,1), 256>>>(att, 0, 128, divw, 0, 128, xd, 0, 128, 128, 1.f, divb, 1, x1,
                                      nullptr, nullptr, nullptr, nullptr);
    gemm_tf32<<<dim3(512,1,1), 256>>>(xd, 0, 128, fc2w, 0, 128, x2, 0, 128, 128, 1.f, fc2b, 1, nullptr,
                                      nullptr, nullptr, nullptr, nullptr);
    gemm_tf32<<<dim3(512,1,1), 256>>>(att, 0, 128, fc3aw, 0, 128, x3a, 0, 128, 128, 1.f, fc3ab, 1, nullptr,
                                      tmean, trstd, ln3g, ln3b);
    gemm_tf32<<<dim3(512,1,1), 256>>>(x3a, 0, 128, fc3bw, 0, 128, x3, 0, 128, 128, 1.f, fc3bb, 0, nullptr,
                                      nullptr, nullptr, nullptr, nullptr);
    gemm_tf32<<<dim3(512,1,1), 256>>>(att, 0, 128, actw, 0, 128, gate, 0, 128, 128, 1.f, actb, 2, nullptr,
                                      nullptr, nullptr, nullptr, nullptr);
    // 8. ffn = gate * ln(x2+x3)
    ln_final<<<8192, 256>>>(x2, x3, gate, lnng, lnnb, ffn);
    // 9. fused implicit-GEMM l1 conv
    conv_l1_tf32<<<dim3(32,1,16), 256>>>(x, l1w, l1b, dw);
    // 10. combine
    final_kernel<<<dim3(64,4,16), 256>>>(x, ffn, y, dw, out);
}